// round 1
// baseline (speedup 1.0000x reference)
#include <cuda_runtime.h>
#include <cuda_bf16.h>

#define DIM     256
#define BATCH   16
#define M_ITEMS 30000

#define MTILE   64
#define KCHUNK  64
#define ITEM_STRIDE 68      // floats per k-row of item tile (pad for banks, 16B aligned)
#define IP_STRIDE   260     // floats per m-row of iproj tile (pad for banks, 16B aligned)

// scratch: u_proj + b1, computed by kernel 1
__device__ float g_up[BATCH * DIM];

// ---------------------------------------------------------------------------
// Kernel 1: g_up[b][d] = sum_k user_table[inst[b]][k] * W1[k][d] + b1[d]
// ---------------------------------------------------------------------------
__global__ void uproj_kernel(const int* __restrict__ inst,
                             const float* __restrict__ user_table,
                             const float* __restrict__ W1,
                             const float* __restrict__ b1) {
    __shared__ float u_sh[DIM];
    int b = blockIdx.x;
    int d = threadIdx.x;
    int row = inst[b];
    u_sh[d] = user_table[(long long)row * DIM + d];
    __syncthreads();
    float s = 0.f;
#pragma unroll 8
    for (int k = 0; k < DIM; k++)
        s = fmaf(u_sh[k], W1[k * DIM + d], s);
    g_up[b * DIM + d] = s + b1[d];
}

// ---------------------------------------------------------------------------
// Kernel 2: per 64-item tile:
//   phase A: iproj[m][d] = item_table[m] @ Wi   (register-blocked SGEMM)
//   phase B: ratings[b][m] = sum_d relu(up[b][d] + iproj[m][d]) * W2[d] + b2
// ---------------------------------------------------------------------------
__global__ __launch_bounds__(256, 2)
void rank_kernel(const float* __restrict__ item_table,
                 const float* __restrict__ W1,
                 const float* __restrict__ W2,
                 const float* __restrict__ b2,
                 float* __restrict__ out) {
    extern __shared__ float sh[];
    // main-phase layout
    float* item_sh = sh;                                // KCHUNK * ITEM_STRIDE
    float* wi_sh   = sh + KCHUNK * ITEM_STRIDE;         // KCHUNK * DIM
    // epilogue layout (reuses same memory)
    float* ip_sh   = sh;                                // MTILE * IP_STRIDE
    float* up_sh   = sh + MTILE * IP_STRIDE;            // BATCH * DIM
    float* w2_sh   = up_sh + BATCH * DIM;               // DIM

    const int t    = threadIdx.x;
    const int lane = t & 31;
    const int warp = t >> 5;
    const int m_base = blockIdx.x * MTILE;
    const int d0 = lane * 8;   // this thread's 8 output dims
    const int m0 = warp * 8;   // this thread's 8 items (same across warp -> smem broadcast)

    const float* Wi = W1 + DIM * DIM;   // W1[256:] rows

    float acc[8][8];
#pragma unroll
    for (int i = 0; i < 8; i++)
#pragma unroll
        for (int j = 0; j < 8; j++) acc[i][j] = 0.f;

    // ---- phase A: iproj tile = item_tile @ Wi --------------------------------
    for (int kc = 0; kc < DIM; kc += KCHUNK) {
        __syncthreads();
        // item chunk, transposed: item_sh[k][m] = item_table[m_base+m][kc+k]
        for (int idx = t; idx < MTILE * KCHUNK; idx += 256) {
            int m = idx >> 6;          // 0..63
            int k = idx & 63;          // 0..63 (consecutive t -> consecutive k: coalesced)
            int gm = m_base + m;
            float v = (gm < M_ITEMS) ? item_table[gm * DIM + kc + k] : 0.f;
            item_sh[k * ITEM_STRIDE + m] = v;
        }
        // Wi chunk: contiguous float4 copy (L2-resident after first wave)
        {
            const float4* wsrc = (const float4*)(Wi + kc * DIM);
            float4* wdst = (float4*)wi_sh;
            for (int idx = t; idx < KCHUNK * DIM / 4; idx += 256)
                wdst[idx] = wsrc[idx];
        }
        __syncthreads();

#pragma unroll 4
        for (int kk = 0; kk < KCHUNK; kk++) {
            float4 a0 = *(const float4*)&item_sh[kk * ITEM_STRIDE + m0];
            float4 a1 = *(const float4*)&item_sh[kk * ITEM_STRIDE + m0 + 4];
            float4 w0 = *(const float4*)&wi_sh[kk * DIM + d0];
            float4 w1 = *(const float4*)&wi_sh[kk * DIM + d0 + 4];
            float a[8] = {a0.x, a0.y, a0.z, a0.w, a1.x, a1.y, a1.z, a1.w};
            float w[8] = {w0.x, w0.y, w0.z, w0.w, w1.x, w1.y, w1.z, w1.w};
#pragma unroll
            for (int i = 0; i < 8; i++)
#pragma unroll
                for (int j = 0; j < 8; j++)
                    acc[i][j] = fmaf(a[i], w[j], acc[i][j]);
        }
    }

    // ---- stage iproj tile + epilogue operands into smem ----------------------
    __syncthreads();
#pragma unroll
    for (int i = 0; i < 8; i++) {
        float4 v0 = make_float4(acc[i][0], acc[i][1], acc[i][2], acc[i][3]);
        float4 v1 = make_float4(acc[i][4], acc[i][5], acc[i][6], acc[i][7]);
        *(float4*)&ip_sh[(m0 + i) * IP_STRIDE + d0]     = v0;
        *(float4*)&ip_sh[(m0 + i) * IP_STRIDE + d0 + 4] = v1;
    }
    for (int idx = t; idx < BATCH * DIM; idx += 256)
        up_sh[idx] = g_up[idx];
    w2_sh[t] = W2[t];   // W2 is (256,1) contiguous
    __syncthreads();

    // ---- phase B: fused relu-dot ---------------------------------------------
    const int m  = t & 63;      // consecutive lanes -> consecutive m (stride 260: no conflicts)
    const int bb = t >> 6;      // 0..3 (constant within a warp -> up_sh broadcast)
    const float bias = __ldg(b2);
    const int gm = m_base + m;
    const float4* iprow = (const float4*)&ip_sh[m * IP_STRIDE];
    const float4* w2v   = (const float4*)w2_sh;

#pragma unroll
    for (int bi = 0; bi < 4; bi++) {
        int b = bb + bi * 4;
        const float4* uprow = (const float4*)&up_sh[b * DIM];
        float r = 0.f;
#pragma unroll 8
        for (int dq = 0; dq < DIM / 4; dq++) {
            float4 ip = iprow[dq];
            float4 u  = uprow[dq];
            float4 w  = w2v[dq];
            r = fmaf(fmaxf(u.x + ip.x, 0.f), w.x, r);
            r = fmaf(fmaxf(u.y + ip.y, 0.f), w.y, r);
            r = fmaf(fmaxf(u.z + ip.z, 0.f), w.z, r);
            r = fmaf(fmaxf(u.w + ip.w, 0.f), w.w, r);
        }
        if (gm < M_ITEMS)
            out[b * M_ITEMS + gm] = r + bias;
    }
}

// ---------------------------------------------------------------------------
extern "C" void kernel_launch(void* const* d_in, const int* in_sizes, int n_in,
                              void* d_out, int out_size) {
    const int*   inst       = (const int*)  d_in[0];
    const float* user_table = (const float*)d_in[1];
    const float* item_table = (const float*)d_in[2];
    const float* W1         = (const float*)d_in[3];
    const float* b1         = (const float*)d_in[4];
    const float* W2         = (const float*)d_in[5];
    const float* b2         = (const float*)d_in[6];
    float* out = (float*)d_out;

    uproj_kernel<<<BATCH, DIM>>>(inst, user_table, W1, b1);

    const int smem_bytes = (MTILE * IP_STRIDE + BATCH * DIM + DIM) * sizeof(float); // 83968
    static_assert((MTILE * IP_STRIDE + BATCH * DIM + DIM) >=
                  (KCHUNK * ITEM_STRIDE + KCHUNK * DIM), "smem union too small");
    cudaFuncSetAttribute(rank_kernel, cudaFuncAttributeMaxDynamicSharedMemorySize, smem_bytes);

    const int nblk = (M_ITEMS + MTILE - 1) / MTILE;   // 469
    rank_kernel<<<nblk, 256, smem_bytes>>>(item_table, W1, W2, b2, out);
}

// round 4
// speedup vs baseline: 1.6027x; 1.6027x over previous
#include <cuda_runtime.h>
#include <cuda_bf16.h>
#include <cstdint>

#define DIM     256
#define BATCH   16
#define M_ITEMS 30000
#define MT      64
#define NTILES  ((M_ITEMS + MT - 1) / MT)    // 469

#define ASTB    144        // padded row pitch (bytes) for 64 bf16 + pad (conflict-free ldmatrix)

// ---------------- smem byte offsets ----------------
#define SM_UP    0          // 16*256 f32   = 16384
#define SM_W2    16384      // 256 f32      = 1024
#define SM_AH    17408      // 64 rows * 144B = 9216
#define SM_AL    26624      // 9216
#define SM_WH    35840      // 256 rows * 144B = 36864
#define SM_WL    72704      // 36864
#define SM_TOTAL 109568
#define SM_RED   SM_WH      // reused after GEMM: 8*64*17 f32 = 34816 <= 36864
#define REDW     1088       // 64*17 floats per warp

__device__ float          g_up[BATCH * DIM];
__device__ __align__(16) __nv_bfloat16 g_wi_hi[DIM * DIM];   // [n][k]
__device__ __align__(16) __nv_bfloat16 g_wi_lo[DIM * DIM];

// ---------------- helpers ----------------
__device__ __forceinline__ uint32_t smem_u32(const void* p) {
    uint32_t a;
    asm("{ .reg .u64 t; cvta.to.shared.u64 t, %1; cvt.u32.u64 %0, t; }" : "=r"(a) : "l"(p));
    return a;
}
__device__ __forceinline__ void ldsm_x4(uint32_t* r, uint32_t addr) {
    asm volatile("ldmatrix.sync.aligned.m8n8.x4.shared.b16 {%0,%1,%2,%3}, [%4];"
                 : "=r"(r[0]), "=r"(r[1]), "=r"(r[2]), "=r"(r[3]) : "r"(addr));
}
__device__ __forceinline__ void mma_bf16(float* c, const uint32_t* a, const uint32_t* b) {
    asm volatile("mma.sync.aligned.m16n8k16.row.col.f32.bf16.bf16.f32 "
                 "{%0,%1,%2,%3}, {%4,%5,%6,%7}, {%8,%9}, {%0,%1,%2,%3};"
                 : "+f"(c[0]), "+f"(c[1]), "+f"(c[2]), "+f"(c[3])
                 : "r"(a[0]), "r"(a[1]), "r"(a[2]), "r"(a[3]), "r"(b[0]), "r"(b[1]));
}
__device__ __forceinline__ uint32_t packbf(float a, float b) {
    __nv_bfloat162 t = __floats2bfloat162_rn(a, b);
    return *reinterpret_cast<uint32_t*>(&t);
}

// ---------------------------------------------------------------------------
// Prep 1: g_up[b][d] = user_table[inst[b]] @ Wu + b1
// ---------------------------------------------------------------------------
__global__ void uproj_kernel(const int* __restrict__ inst,
                             const float* __restrict__ user_table,
                             const float* __restrict__ W1,
                             const float* __restrict__ b1) {
    __shared__ float u_sh[DIM];
    int b = blockIdx.x, d = threadIdx.x;
    u_sh[d] = user_table[(long long)inst[b] * DIM + d];
    __syncthreads();
    float s = 0.f;
#pragma unroll 8
    for (int k = 0; k < DIM; k++) s = fmaf(u_sh[k], W1[k * DIM + d], s);
    g_up[b * DIM + d] = s + b1[d];
}

// ---------------------------------------------------------------------------
// Prep 2: transpose+split Wi: g_wi_{hi,lo}[n][k] = split(W1[256+k][n])
// (coalesced reads, scattered writes)
// ---------------------------------------------------------------------------
__global__ void wprep_kernel(const float* __restrict__ W1) {
    int k = blockIdx.x, n = threadIdx.x;
    float v = W1[(DIM + k) * DIM + n];
    __nv_bfloat16 h = __float2bfloat16(v);
    g_wi_hi[n * DIM + k] = h;
    g_wi_lo[n * DIM + k] = __float2bfloat16(v - __bfloat162float(h));
}

// ---------------------------------------------------------------------------
// Main: 64-item tile per CTA. GEMM via mma.sync bf16 (3-term split), fused
// relu-dot epilogue from register accumulators.
// ---------------------------------------------------------------------------
__global__ __launch_bounds__(256, 1)
void rank_mma_kernel(const float* __restrict__ item_table,
                     const float* __restrict__ W2,
                     const float* __restrict__ b2,
                     float* __restrict__ out) {
    extern __shared__ __align__(16) char smem[];
    const uint32_t sb = smem_u32(smem);
    const int t = threadIdx.x;
    const int w = t >> 5;            // warp 0..7 : n-slice [32w, 32w+32)
    const int l = t & 31;
    const int m_base = blockIdx.x * MT;

    float* up_sh = (float*)(smem + SM_UP);
    float* w2_sh = (float*)(smem + SM_W2);
    for (int idx = t; idx < BATCH * DIM; idx += 256) up_sh[idx] = g_up[idx];
    w2_sh[t] = W2[t];

    // per-lane ldmatrix address components
    const uint32_t a_off = (uint32_t)(l & 15) * ASTB + ((l >> 4) * 8) * 2;
    const uint32_t b_row = (uint32_t)(w * 32 + (l & 7) + ((l >> 4) & 1) * 8);
    const uint32_t b_off = b_row * ASTB + (((l >> 3) & 1) * 8) * 2;

    float acc[4][4][4];              // [mt][nt][v]
#pragma unroll
    for (int i = 0; i < 4; i++)
#pragma unroll
        for (int j = 0; j < 4; j++)
#pragma unroll
            for (int v = 0; v < 4; v++) acc[i][j][v] = 0.f;

    // ---------------- GEMM: 4 k-chunks of 64 ----------------
    for (int kc = 0; kc < 4; kc++) {
        __syncthreads();   // previous iteration's ldmatrix reads complete
        // A: load fp32 item rows, split hi/lo, store padded rows
        for (int idx = t; idx < MT * 8; idx += 256) {
            int row = idx >> 3, g = idx & 7;
            int gm = m_base + row;
            float v[8];
            if (gm < M_ITEMS) {
                const float4* src = (const float4*)(item_table + (long long)gm * DIM + kc * 64 + g * 8);
                float4 p0 = src[0], p1 = src[1];
                v[0] = p0.x; v[1] = p0.y; v[2] = p0.z; v[3] = p0.w;
                v[4] = p1.x; v[5] = p1.y; v[6] = p1.z; v[7] = p1.w;
            } else {
#pragma unroll
                for (int i = 0; i < 8; i++) v[i] = 0.f;
            }
            float lo[8];
#pragma unroll
            for (int i = 0; i < 8; i++)
                lo[i] = v[i] - __bfloat162float(__float2bfloat16(v[i]));
            uint4 HI = make_uint4(packbf(v[0], v[1]), packbf(v[2], v[3]),
                                  packbf(v[4], v[5]), packbf(v[6], v[7]));
            uint4 LO = make_uint4(packbf(lo[0], lo[1]), packbf(lo[2], lo[3]),
                                  packbf(lo[4], lo[5]), packbf(lo[6], lo[7]));
            *(uint4*)(smem + SM_AH + row * ASTB + g * 16) = HI;
            *(uint4*)(smem + SM_AL + row * ASTB + g * 16) = LO;
        }
        // B: copy pre-split Wi chunk into padded rows
        for (int idx = t; idx < DIM * 8; idx += 256) {
            int n = idx >> 3, g = idx & 7;
            uint4 H = *(const uint4*)&g_wi_hi[n * DIM + kc * 64 + g * 8];
            uint4 L = *(const uint4*)&g_wi_lo[n * DIM + kc * 64 + g * 8];
            *(uint4*)(smem + SM_WH + n * ASTB + g * 16) = H;
            *(uint4*)(smem + SM_WL + n * ASTB + g * 16) = L;
        }
        __syncthreads();

#pragma unroll
        for (int ks = 0; ks < 4; ks++) {
            const uint32_t kb = (uint32_t)(ks * 32);
            uint32_t ah[4][4], al[4][4], bh[2][4], bl[2][4];
#pragma unroll
            for (int mt = 0; mt < 4; mt++)
                ldsm_x4(ah[mt], sb + SM_AH + a_off + mt * (16 * ASTB) + kb);
#pragma unroll
            for (int np = 0; np < 2; np++)
                ldsm_x4(bh[np], sb + SM_WH + b_off + np * (16 * ASTB) + kb);
            // hi * hi
#pragma unroll
            for (int mt = 0; mt < 4; mt++)
#pragma unroll
                for (int nt = 0; nt < 4; nt++)
                    mma_bf16(acc[mt][nt], ah[mt], &bh[nt >> 1][(nt & 1) * 2]);
            // hi * lo
#pragma unroll
            for (int np = 0; np < 2; np++)
                ldsm_x4(bl[np], sb + SM_WL + b_off + np * (16 * ASTB) + kb);
#pragma unroll
            for (int mt = 0; mt < 4; mt++)
#pragma unroll
                for (int nt = 0; nt < 4; nt++)
                    mma_bf16(acc[mt][nt], ah[mt], &bl[nt >> 1][(nt & 1) * 2]);
            // lo * hi
#pragma unroll
            for (int mt = 0; mt < 4; mt++)
                ldsm_x4(al[mt], sb + SM_AL + a_off + mt * (16 * ASTB) + kb);
#pragma unroll
            for (int mt = 0; mt < 4; mt++)
#pragma unroll
                for (int nt = 0; nt < 4; nt++)
                    mma_bf16(acc[mt][nt], al[mt], &bh[nt >> 1][(nt & 1) * 2]);
        }
    }

    __syncthreads();        // all warps done reading wi region -> reuse as red

    // ---------------- epilogue: fused relu-dot from registers ----------------
    const int g  = l >> 2;          // fragment row group
    const int tq = l & 3;           // fragment col group
    float* red = (float*)(smem + SM_RED);

    float w2v[4][2];
#pragma unroll
    for (int nt = 0; nt < 4; nt++) {
        float2 wv = *(const float2*)&w2_sh[w * 32 + nt * 8 + tq * 2];
        w2v[nt][0] = wv.x; w2v[nt][1] = wv.y;
    }

#pragma unroll 1
    for (int b = 0; b < BATCH; b++) {
        float p[8];
#pragma unroll
        for (int i = 0; i < 8; i++) p[i] = 0.f;
#pragma unroll
        for (int nt = 0; nt < 4; nt++) {
            float2 u = *(const float2*)&up_sh[b * DIM + w * 32 + nt * 8 + tq * 2];
#pragma unroll
            for (int mt = 0; mt < 4; mt++) {
                p[mt * 2 + 0] = fmaf(fmaxf(acc[mt][nt][0] + u.x, 0.f), w2v[nt][0], p[mt * 2 + 0]);
                p[mt * 2 + 0] = fmaf(fmaxf(acc[mt][nt][1] + u.y, 0.f), w2v[nt][1], p[mt * 2 + 0]);
                p[mt * 2 + 1] = fmaf(fmaxf(acc[mt][nt][2] + u.x, 0.f), w2v[nt][0], p[mt * 2 + 1]);
                p[mt * 2 + 1] = fmaf(fmaxf(acc[mt][nt][3] + u.y, 0.f), w2v[nt][1], p[mt * 2 + 1]);
            }
        }
        // reduce across the 4 tq lanes
#pragma unroll
        for (int i = 0; i < 8; i++) {
            p[i] += __shfl_xor_sync(0xFFFFFFFF, p[i], 1);
            p[i] += __shfl_xor_sync(0xFFFFFFFF, p[i], 2);
        }
        if (tq == 0) {
#pragma unroll
            for (int i = 0; i < 8; i++) {
                int m = (i >> 1) * 16 + g + (i & 1) * 8;
                red[w * REDW + m * 17 + b] = p[i];
            }
        }
    }
    __syncthreads();

    // ---------------- combine 8 warp partials, write out ----------------
    const float bias = __ldg(b2);
    const int m  = t & 63;
    const int b0 = (t >> 6) * 4;
    const int gm = m_base + m;
#pragma unroll
    for (int i = 0; i < 4; i++) {
        int b = b0 + i;
        float s = bias;
#pragma unroll
        for (int w8 = 0; w8 < 8; w8++)
            s += red[w8 * REDW + m * 17 + b];
        if (gm < M_ITEMS)
            out[b * M_ITEMS + gm] = s;
    }
}

// ---------------------------------------------------------------------------
extern "C" void kernel_launch(void* const* d_in, const int* in_sizes, int n_in,
                              void* d_out, int out_size) {
    const int*   inst       = (const int*)  d_in[0];
    const float* user_table = (const float*)d_in[1];
    const float* item_table = (const float*)d_in[2];
    const float* W1         = (const float*)d_in[3];
    const float* b1         = (const float*)d_in[4];
    const float* W2         = (const float*)d_in[5];
    const float* b2         = (const float*)d_in[6];
    float* out = (float*)d_out;

    uproj_kernel<<<BATCH, DIM>>>(inst, user_table, W1, b1);
    wprep_kernel<<<DIM, DIM>>>(W1);

    cudaFuncSetAttribute(rank_mma_kernel, cudaFuncAttributeMaxDynamicSharedMemorySize, SM_TOTAL);
    rank_mma_kernel<<<NTILES, 256, SM_TOTAL>>>(item_table, W2, b2, out);
}

// round 5
// speedup vs baseline: 2.1486x; 1.3406x over previous
#include <cuda_runtime.h>
#include <cuda_bf16.h>
#include <cstdint>

#define DIM     256
#define BATCH   16
#define M_ITEMS 30000
#define MT      128
#define NTILES  ((M_ITEMS + MT - 1) / MT)    // 235
#define ASTB    144        // padded row pitch (bytes): 64 bf16 + 16B pad

// ---------------- smem byte offsets (dynamic) ----------------
#define SM_W2    0          // 256 f32 = 1024
#define SM_AH0   1024       // 128*144 = 18432
#define SM_AL0   19456
#define SM_AH1   37888
#define SM_AL1   56320
#define SM_BH0   74752      // 256*144 = 36864
#define SM_BL0   111616
#define SM_BH1   148480
#define SM_BL1   185344
#define SM_TOTAL 222208
#define SM_RED   SM_BH0     // epilogue reuse: 8 warps * 128*17 f32 = 69632 <= 73728
#define SM_UPE   SM_BH1     // epilogue reuse: 16*256 f32 = 16384
#define REDW     2176       // 128*17 floats per warp

__device__ float          g_up[BATCH * DIM];
__device__ __align__(16) __nv_bfloat16 g_wi_hi[DIM * DIM];   // [n][k]
__device__ __align__(16) __nv_bfloat16 g_wi_lo[DIM * DIM];

// ---------------- helpers ----------------
__device__ __forceinline__ uint32_t smem_u32(const void* p) {
    uint32_t a;
    asm("{ .reg .u64 t; cvta.to.shared.u64 t, %1; cvt.u32.u64 %0, t; }" : "=r"(a) : "l"(p));
    return a;
}
__device__ __forceinline__ void ldsm_x4(uint32_t* r, uint32_t addr) {
    asm volatile("ldmatrix.sync.aligned.m8n8.x4.shared.b16 {%0,%1,%2,%3}, [%4];"
                 : "=r"(r[0]), "=r"(r[1]), "=r"(r[2]), "=r"(r[3]) : "r"(addr));
}
__device__ __forceinline__ void mma_bf16(float* c, const uint32_t* a, const uint32_t* b) {
    asm volatile("mma.sync.aligned.m16n8k16.row.col.f32.bf16.bf16.f32 "
                 "{%0,%1,%2,%3}, {%4,%5,%6,%7}, {%8,%9}, {%0,%1,%2,%3};"
                 : "+f"(c[0]), "+f"(c[1]), "+f"(c[2]), "+f"(c[3])
                 : "r"(a[0]), "r"(a[1]), "r"(a[2]), "r"(a[3]), "r"(b[0]), "r"(b[1]));
}
__device__ __forceinline__ void cpasync16(uint32_t dst, const void* src) {
    asm volatile("cp.async.cg.shared.global [%0], [%1], 16;" :: "r"(dst), "l"(src));
}
#define CP_COMMIT() asm volatile("cp.async.commit_group;" ::: "memory")
#define CP_WAIT0()  asm volatile("cp.async.wait_group 0;" ::: "memory")

__device__ __forceinline__ uint32_t packbf(float a, float b) {
    __nv_bfloat162 t = __floats2bfloat162_rn(a, b);
    return *reinterpret_cast<uint32_t*>(&t);
}

// ---------------------------------------------------------------------------
// Fused prep kernel (384 blocks):
//   blocks [0,256):   wprep — g_wi_{hi,lo}[n][k] = split(W1[256+k][n])
//   blocks [256,384): uproj — g_up[b][d] = user_table[inst[b]] @ Wu + b1
// ---------------------------------------------------------------------------
__global__ void prep_kernel(const int* __restrict__ inst,
                            const float* __restrict__ user_table,
                            const float* __restrict__ W1,
                            const float* __restrict__ b1) {
    const int bx = blockIdx.x, t = threadIdx.x;
    if (bx < 256) {
        // wprep: row (256+bx) of W1, coalesced read over n
        float v = W1[(DIM + bx) * DIM + t];
        __nv_bfloat16 h = __float2bfloat16(v);
        g_wi_hi[t * DIM + bx] = h;
        g_wi_lo[t * DIM + bx] = __float2bfloat16(v - __bfloat162float(h));
    } else {
        // uproj: block id -> (b, 32-col slice c); threads: (ks 8) x (d_local 32)
        __shared__ float u_sh[DIM];
        __shared__ float part[8][33];
        const int id = bx - 256;
        const int b = id >> 3, c = id & 7;
        const int d0 = c * 32;
        const int dl = t & 31, ks = t >> 5;
        u_sh[t] = user_table[(long long)inst[b] * DIM + t];
        __syncthreads();
        float s = 0.f;
#pragma unroll 8
        for (int kk = 0; kk < 32; kk++) {
            int k = ks * 32 + kk;
            s = fmaf(u_sh[k], W1[k * DIM + d0 + dl], s);
        }
        part[ks][dl] = s;
        __syncthreads();
        if (t < 32) {
            float r = b1[d0 + t];
#pragma unroll
            for (int j = 0; j < 8; j++) r += part[j][t];
            g_up[b * DIM + d0 + t] = r;
        }
    }
}

// ---------------------------------------------------------------------------
// A chunk converter: fp32 item rows -> bf16 hi/lo in padded smem rows
// ---------------------------------------------------------------------------
__device__ __forceinline__ void load_a_chunk(char* smem, int hi_off, int lo_off,
                                             const float* __restrict__ item_table,
                                             int m_base, int kc, int t) {
#pragma unroll
    for (int it = 0; it < 4; it++) {
        int idx = t + it * 256;
        int row = idx >> 3, g = idx & 7;
        int gm = m_base + row;
        float v[8];
        if (gm < M_ITEMS) {
            const float4* src = (const float4*)(item_table + (long long)gm * DIM + kc * 64 + g * 8);
            float4 p0 = src[0], p1 = src[1];
            v[0] = p0.x; v[1] = p0.y; v[2] = p0.z; v[3] = p0.w;
            v[4] = p1.x; v[5] = p1.y; v[6] = p1.z; v[7] = p1.w;
        } else {
#pragma unroll
            for (int i = 0; i < 8; i++) v[i] = 0.f;
        }
        float lo[8];
#pragma unroll
        for (int i = 0; i < 8; i++)
            lo[i] = v[i] - __bfloat162float(__float2bfloat16(v[i]));
        uint4 HI = make_uint4(packbf(v[0], v[1]), packbf(v[2], v[3]),
                              packbf(v[4], v[5]), packbf(v[6], v[7]));
        uint4 LO = make_uint4(packbf(lo[0], lo[1]), packbf(lo[2], lo[3]),
                              packbf(lo[4], lo[5]), packbf(lo[6], lo[7]));
        *(uint4*)(smem + hi_off + row * ASTB + g * 16) = HI;
        *(uint4*)(smem + lo_off + row * ASTB + g * 16) = LO;
    }
}

// B chunk via cp.async into padded smem rows
__device__ __forceinline__ void load_b_chunk(uint32_t sb, int hi_off, int lo_off,
                                             int kc, int t) {
#pragma unroll
    for (int it = 0; it < 8; it++) {
        int idx = t + it * 256;
        int n = idx >> 3, g = idx & 7;
        uint32_t d = (uint32_t)(n * ASTB + g * 16);
        const __nv_bfloat16* sh = &g_wi_hi[n * DIM + kc * 64 + g * 8];
        const __nv_bfloat16* sl = &g_wi_lo[n * DIM + kc * 64 + g * 8];
        cpasync16(sb + hi_off + d, sh);
        cpasync16(sb + lo_off + d, sl);
    }
}

// ---------------------------------------------------------------------------
// Main kernel: 128-item tile per CTA, double-buffered bf16 3-term mma.sync GEMM,
// fused relu-dot epilogue from registers.
// ---------------------------------------------------------------------------
__global__ __launch_bounds__(256, 1)
void rank_mma_kernel(const float* __restrict__ item_table,
                     const float* __restrict__ W2,
                     const float* __restrict__ b2,
                     float* __restrict__ out) {
    extern __shared__ __align__(16) char smem[];
    const uint32_t sb = smem_u32(smem);
    const int t = threadIdx.x;
    const int w = t >> 5;            // warp 0..7 : n-slice [32w, 32w+32)
    const int l = t & 31;
    const int m_base = blockIdx.x * MT;

    float* w2_sh = (float*)(smem + SM_W2);
    w2_sh[t] = W2[t];

    const uint32_t a_off = (uint32_t)(l & 15) * ASTB + ((l >> 4) * 8) * 2;
    const uint32_t b_row = (uint32_t)(w * 32 + (l & 7) + ((l >> 4) & 1) * 8);
    const uint32_t b_off = b_row * ASTB + (((l >> 3) & 1) * 8) * 2;

    float acc[8][4][4];
#pragma unroll
    for (int i = 0; i < 8; i++)
#pragma unroll
        for (int j = 0; j < 4; j++)
#pragma unroll
            for (int v = 0; v < 4; v++) acc[i][j][v] = 0.f;

    // prologue: chunk 0 into buffer 0
    load_b_chunk(sb, SM_BH0, SM_BL0, 0, t);
    CP_COMMIT();
    load_a_chunk(smem, SM_AH0, SM_AL0, item_table, m_base, 0, t);
    CP_WAIT0();
    __syncthreads();

    const int AH[2] = {SM_AH0, SM_AH1}, AL[2] = {SM_AL0, SM_AL1};
    const int BH[2] = {SM_BH0, SM_BH1}, BL[2] = {SM_BL0, SM_BL1};

#pragma unroll
    for (int kc = 0; kc < 4; kc++) {
        const int cur = kc & 1, nxt = cur ^ 1;
        if (kc < 3) {
            load_b_chunk(sb, BH[nxt], BL[nxt], kc + 1, t);
            CP_COMMIT();
            load_a_chunk(smem, AH[nxt], AL[nxt], item_table, m_base, kc + 1, t);
        }
        // ---- MMA on buffer cur ----
        const uint32_t ah_base = sb + AH[cur] + a_off;
        const uint32_t al_base = sb + AL[cur] + a_off;
        const uint32_t bh_base = sb + BH[cur] + b_off;
        const uint32_t bl_base = sb + BL[cur] + b_off;
#pragma unroll
        for (int ks = 0; ks < 4; ks++) {
            const uint32_t kb = (uint32_t)(ks * 32);
            uint32_t bhf[2][4], blf[2][4];
#pragma unroll
            for (int np = 0; np < 2; np++) {
                ldsm_x4(bhf[np], bh_base + np * (16 * ASTB) + kb);
                ldsm_x4(blf[np], bl_base + np * (16 * ASTB) + kb);
            }
#pragma unroll
            for (int mt = 0; mt < 8; mt++) {
                uint32_t ah[4], al[4];
                ldsm_x4(ah, ah_base + mt * (16 * ASTB) + kb);
                ldsm_x4(al, al_base + mt * (16 * ASTB) + kb);
#pragma unroll
                for (int nt = 0; nt < 4; nt++) {
                    mma_bf16(acc[mt][nt], ah, &bhf[nt >> 1][(nt & 1) * 2]);
                    mma_bf16(acc[mt][nt], ah, &blf[nt >> 1][(nt & 1) * 2]);
                    mma_bf16(acc[mt][nt], al, &bhf[nt >> 1][(nt & 1) * 2]);
                }
            }
        }
        CP_WAIT0();
        __syncthreads();
    }

    // ---------------- epilogue ----------------
    float* up_sh = (float*)(smem + SM_UPE);
    for (int idx = t; idx < BATCH * DIM; idx += 256) up_sh[idx] = g_up[idx];
    __syncthreads();

    const int g  = l >> 2;          // fragment row group 0..7
    const int tq = l & 3;           // fragment col pair 0..3
    float* red = (float*)(smem + SM_RED);

    float w2v[4][2];
#pragma unroll
    for (int nt = 0; nt < 4; nt++) {
        float2 wv = *(const float2*)&w2_sh[w * 32 + nt * 8 + tq * 2];
        w2v[nt][0] = wv.x; w2v[nt][1] = wv.y;
    }

#pragma unroll 1
    for (int b = 0; b < BATCH; b++) {
        float p[16];
#pragma unroll
        for (int i = 0; i < 16; i++) p[i] = 0.f;
#pragma unroll
        for (int nt = 0; nt < 4; nt++) {
            float2 u = *(const float2*)&up_sh[b * DIM + w * 32 + nt * 8 + tq * 2];
#pragma unroll
            for (int mt = 0; mt < 8; mt++) {
                p[mt * 2 + 0] = fmaf(fmaxf(acc[mt][nt][0] + u.x, 0.f), w2v[nt][0], p[mt * 2 + 0]);
                p[mt * 2 + 0] = fmaf(fmaxf(acc[mt][nt][1] + u.y, 0.f), w2v[nt][1], p[mt * 2 + 0]);
                p[mt * 2 + 1] = fmaf(fmaxf(acc[mt][nt][2] + u.x, 0.f), w2v[nt][0], p[mt * 2 + 1]);
                p[mt * 2 + 1] = fmaf(fmaxf(acc[mt][nt][3] + u.y, 0.f), w2v[nt][1], p[mt * 2 + 1]);
            }
        }
#pragma unroll
        for (int i = 0; i < 16; i++) {
            p[i] += __shfl_xor_sync(0xFFFFFFFF, p[i], 1);
            p[i] += __shfl_xor_sync(0xFFFFFFFF, p[i], 2);
        }
        if (tq == 0) {
#pragma unroll
            for (int i = 0; i < 16; i++) {
                int m = (i >> 1) * 16 + g + (i & 1) * 8;
                red[w * REDW + m * 17 + b] = p[i];
            }
        }
    }
    __syncthreads();

    // combine 8 warp partials, write out
    const float bias = __ldg(b2);
    const int m  = t & 127;
    const int b0 = (t >> 7) * 8;
    const int gm = m_base + m;
#pragma unroll
    for (int i = 0; i < 8; i++) {
        int b = b0 + i;
        float s = bias;
#pragma unroll
        for (int w8 = 0; w8 < 8; w8++)
            s += red[w8 * REDW + m * 17 + b];
        if (gm < M_ITEMS)
            out[b * M_ITEMS + gm] = s;
    }
}

// ---------------------------------------------------------------------------
extern "C" void kernel_launch(void* const* d_in, const int* in_sizes, int n_in,
                              void* d_out, int out_size) {
    const int*   inst       = (const int*)  d_in[0];
    const float* user_table = (const float*)d_in[1];
    const float* item_table = (const float*)d_in[2];
    const float* W1         = (const float*)d_in[3];
    const float* b1         = (const float*)d_in[4];
    const float* W2         = (const float*)d_in[5];
    const float* b2         = (const float*)d_in[6];
    float* out = (float*)d_out;

    prep_kernel<<<384, 256>>>(inst, user_table, W1, b1);

    cudaFuncSetAttribute(rank_mma_kernel, cudaFuncAttributeMaxDynamicSharedMemorySize, SM_TOTAL);
    rank_mma_kernel<<<NTILES, 256, SM_TOTAL>>>(item_table, W2, b2, out);
}